// round 11
// baseline (speedup 1.0000x reference)
#include <cuda_runtime.h>
#include <cuda_fp16.h>
#include <stdint.h>

#define NN    50000
#define NE    800000
#define ET    (NE + NN)      // 850000
#define OD    40
#define NEG_SLOPE 0.2f
#define CSRB  49             // csr blocks (all co-resident on 148 SMs)

#define LDA 136              // A smem row stride (halfs)
#define LDB 152              // gemm1 B smem row stride (halfs)
#define LDB2 56              // gemm2 B smem row stride (halfs)

// ---------------- scratch ----------------
__device__ __align__(16) __half g_W1h[128 * 144];  // [W1 | Va | Vd | pad] fp16
__device__ __align__(16) __half g_W2h[128 * 48];   // [W2 | ws | wd | pad] fp16
__device__ __align__(16) uint2  g_h1[NN * 32];     // [NN][128] fp16
__device__ __align__(16) float4 g_acc1[NN * 32];   // [NN][128] fp32 (normalized)
__device__ float4 g_as1[NN];
__device__ float4 g_ad1[NN];
__device__ __align__(16) __half g_h2[NN * OD];     // [NN][40] fp16
__device__ float  g_as2[NN];
__device__ float  g_ad2[NN];
// CSR
__device__ int    g_deg[NN];
__device__ int    g_bsum[64];
__device__ int    g_barc[5];      // spin-barrier counters (self-reset each call)
__device__ int    g_ptr[NN];
__device__ int    g_eoff[ET];
__device__ int    g_esrc[ET];

// ---------------- helpers ----------------
__device__ __forceinline__ float lrelu(float v) { return v > 0.f ? v : NEG_SLOPE * v; }

__device__ __forceinline__ void edge_sd(const int* __restrict__ ei, int e, int& s, int& d) {
    if (e < NE) { s = ei[e]; d = ei[NE + e]; }
    else        { s = d = e - NE; }
}
__device__ __forceinline__ uint32_t smem_u32(const void* p) {
    return (uint32_t)__cvta_generic_to_shared(p);
}
__device__ __forceinline__ void ldmatrix_x4(uint32_t& r0, uint32_t& r1, uint32_t& r2, uint32_t& r3, uint32_t addr) {
    asm volatile("ldmatrix.sync.aligned.m8n8.x4.shared.b16 {%0,%1,%2,%3}, [%4];"
                 : "=r"(r0), "=r"(r1), "=r"(r2), "=r"(r3) : "r"(addr));
}
__device__ __forceinline__ void ldmatrix_x4_trans(uint32_t& r0, uint32_t& r1, uint32_t& r2, uint32_t& r3, uint32_t addr) {
    asm volatile("ldmatrix.sync.aligned.m8n8.x4.trans.shared.b16 {%0,%1,%2,%3}, [%4];"
                 : "=r"(r0), "=r"(r1), "=r"(r2), "=r"(r3) : "r"(addr));
}
__device__ __forceinline__ void mma16816(float* d, uint32_t a0, uint32_t a1, uint32_t a2, uint32_t a3,
                                         uint32_t b0, uint32_t b1) {
    asm volatile("mma.sync.aligned.m16n8k16.row.col.f32.f16.f16.f32 "
                 "{%0,%1,%2,%3}, {%4,%5,%6,%7}, {%8,%9}, {%0,%1,%2,%3};"
                 : "+f"(d[0]), "+f"(d[1]), "+f"(d[2]), "+f"(d[3])
                 : "r"(a0), "r"(a1), "r"(a2), "r"(a3), "r"(b0), "r"(b1));
}

// grid-wide spin barrier (valid: all CSRB blocks co-resident)
__device__ __forceinline__ void gbar(int idx) {
    __threadfence();
    __syncthreads();
    if (threadIdx.x == 0) {
        atomicAdd(&g_barc[idx], 1);
        while (((volatile int*)g_barc)[idx] < CSRB) {}
    }
    __syncthreads();
    __threadfence();
}

// ---------------- prep: W1h + W2h (1 block, 128 threads) ----------------
__global__ void k_prep(const float* __restrict__ W1,
                       const float* __restrict__ a1s, const float* __restrict__ a1d,
                       const float* __restrict__ W2,
                       const float* __restrict__ a2s, const float* __restrict__ a2d) {
    int k = threadIdx.x;   // 128
    // W2h row k: [W2 row | ws | wd | 0-pad]
    {
        __half* d2 = &g_W2h[k * 48];
        float ws = 0.f, wd = 0.f;
        for (int c = 0; c < OD; c++) {
            float w = W2[k * OD + c];
            d2[c] = __float2half_rn(w);
            ws += w * a2s[c];
            wd += w * a2d[c];
        }
        d2[40] = __float2half_rn(ws);
        d2[41] = __float2half_rn(wd);
#pragma unroll
        for (int c = 42; c < 48; c++) d2[c] = __float2half_rn(0.f);
    }
    // W1h row k: [W1 row | Va | Vd | 0-pad]
    {
        __half* dst = &g_W1h[k * 144];
        float va[4] = {0.f, 0.f, 0.f, 0.f}, vd[4] = {0.f, 0.f, 0.f, 0.f};
        for (int c = 0; c < 128; c++) {
            float w = W1[k * 128 + c];
            dst[c] = __float2half_rn(w);
            int h = c >> 5;
            va[h] += w * a1s[c];
            vd[h] += w * a1d[c];
        }
#pragma unroll
        for (int h = 0; h < 4; h++) {
            dst[128 + h] = __float2half_rn(va[h]);
            dst[132 + h] = __float2half_rn(vd[h]);
        }
#pragma unroll
        for (int c = 136; c < 144; c++) dst[c] = __float2half_rn(0.f);
    }
}

// ---------------- fused CSR build: zero + hist + scan + prefix + fill ----------------
__global__ void __launch_bounds__(1024) k_csr(const int* __restrict__ ei) {
    __shared__ int wsum[32];
    __shared__ int s_prefix;
    int t = threadIdx.x, lane = t & 31, wid = t >> 5;
    int b = blockIdx.x;
    int gid = b * 1024 + t;

    // phase 0: zero degrees
    if (gid < NN) g_deg[gid] = 0;
    gbar(0);

    // phase 1: histogram + within-node offsets
    for (int e = gid; e < ET; e += CSRB * 1024) {
        int d = (e < NE) ? ei[NE + e] : (e - NE);
        g_eoff[e] = atomicAdd(&g_deg[d], 1);
    }
    gbar(1);

    // phase 2: block-local inclusive scan of degrees
    int deg = (gid < NN) ? g_deg[gid] : 0;
    int s = deg;
#pragma unroll
    for (int o = 1; o < 32; o <<= 1) {
        int n = __shfl_up_sync(0xffffffffu, s, o);
        if (lane >= o) s += n;
    }
    if (lane == 31) wsum[wid] = s;
    __syncthreads();
    if (wid == 0) {
        int ws = wsum[lane];
#pragma unroll
        for (int o = 1; o < 32; o <<= 1) {
            int n = __shfl_up_sync(0xffffffffu, ws, o);
            if (lane >= o) ws += n;
        }
        wsum[lane] = ws;
    }
    __syncthreads();
    int res = s + (wid ? wsum[wid - 1] : 0);       // inclusive within block
    if (t == 1023) g_bsum[b] = res;
    gbar(2);

    // phase 3: cross-block prefix (all bsums published)
    if (t < 32) {
        int sum = 0;
        for (int p = lane; p < b; p += 32) sum += g_bsum[p];
#pragma unroll
        for (int o = 16; o; o >>= 1) sum += __shfl_xor_sync(0xffffffffu, sum, o);
        if (lane == 0) s_prefix = sum;
    }
    __syncthreads();
    if (gid < NN) g_ptr[gid] = res - deg + s_prefix;
    gbar(3);

    // phase 4: fill (atomic-free)
    for (int e = gid; e < ET; e += CSRB * 1024) {
        int sn, d; edge_sd(ei, e, sn, d);
        g_esrc[g_ptr[d] + g_eoff[e]] = sn;
    }

    // epilogue: reset barrier counters for the next invocation
    __syncthreads();
    if (t == 0) {
        int done = atomicAdd(&g_barc[4], 1);
        if (done == CSRB - 1) {
            g_barc[0] = 0; g_barc[1] = 0; g_barc[2] = 0;
            g_barc[3] = 0; g_barc[4] = 0;
            __threadfence();
        }
    }
}

// ---------------- GEMM1: HMMA, 128 rows/block, N=136 ----------------
__global__ void __launch_bounds__(256) k_gemm1(const float* __restrict__ x) {
    __shared__ __align__(16) __half As[128 * LDA];
    __shared__ __align__(16) __half Bs[16 * LDB];
    int t = threadIdx.x, lane = t & 31, warp = t >> 5;
    int row0 = blockIdx.x * 128;

    for (int i = t; i < 128 * 32; i += 256) {
        int r = i >> 5, c4 = i & 31;
        int gr = min(row0 + r, NN - 1);
        float4 v = ((const float4*)x)[gr * 32 + c4];
        *(__half2*)&As[r * LDA + c4 * 4]     = __floats2half2_rn(v.x, v.y);
        *(__half2*)&As[r * LDA + c4 * 4 + 2] = __floats2half2_rn(v.z, v.w);
    }

    float acc[17][4];
#pragma unroll
    for (int p = 0; p < 17; p++)
#pragma unroll
        for (int q = 0; q < 4; q++) acc[p][q] = 0.f;

    int wrow = warp * 16;
    uint32_t a_row_addr = smem_u32(&As[(wrow + (lane & 15)) * LDA + ((lane >> 4) * 8)]);
    uint32_t b_addr0 = (lane < 16) ? smem_u32(&Bs[(lane & 15) * LDB])
                                   : smem_u32(&Bs[(lane - 16) * LDB + 8]);

    for (int kb = 0; kb < 8; kb++) {
        __syncthreads();
        for (int i = t; i < 288; i += 256) {
            int r = i / 18, c8 = i % 18;
            uint4 v = ((const uint4*)&g_W1h[(kb * 16 + r) * 144])[c8];
            *(uint4*)&Bs[r * LDB + c8 * 8] = v;
        }
        __syncthreads();

        uint32_t a0, a1, a2, a3;
        ldmatrix_x4(a0, a1, a2, a3, a_row_addr + kb * 32);

#pragma unroll
        for (int p = 0; p < 9; p++) {
            uint32_t b0, b1, b2, b3;
            ldmatrix_x4_trans(b0, b1, b2, b3, b_addr0 + p * 32);
            mma16816(acc[2 * p], a0, a1, a2, a3, b0, b1);
            if (p < 8) mma16816(acc[2 * p + 1], a0, a1, a2, a3, b2, b3);
        }
    }
    __syncthreads();

    int g = lane >> 2, c0 = (lane & 3) * 2;
    {
        int r_lo = row0 + wrow + g, r_hi = r_lo + 8;
#pragma unroll
        for (int q = 0; q < 4; q++) {
            int row = (q < 2) ? r_lo : r_hi;
            int c = c0 + (q & 1);
            if (row < NN) {
                if (c < 4) ((float*)&g_as1[row])[c] = acc[16][q];
                else       ((float*)&g_ad1[row])[c - 4] = acc[16][q];
            }
        }
    }

#pragma unroll
    for (int tl = 0; tl < 16; tl++) {
        *(__half2*)&As[(wrow + g) * LDA + tl * 8 + c0]     = __floats2half2_rn(acc[tl][0], acc[tl][1]);
        *(__half2*)&As[(wrow + g + 8) * LDA + tl * 8 + c0] = __floats2half2_rn(acc[tl][2], acc[tl][3]);
    }
    __syncthreads();
    for (int i = t; i < 128 * 16; i += 256) {
        int r = i >> 4, c16 = i & 15;
        int row = row0 + r;
        if (row < NN) ((uint4*)g_h1)[row * 16 + c16] = *(const uint4*)&As[r * LDA + c16 * 8];
    }
}

// ---------------- layer-1 aggregation (R10 version) ----------------
__global__ void __launch_bounds__(256) k_agg1() {
    __shared__ int    s_src[8][32];
    __shared__ float4 s_al[8][32];
    int gw = (blockIdx.x * 256 + threadIdx.x) >> 5;
    if (gw >= NN) return;
    int lane = threadIdx.x & 31;
    int wb = threadIdx.x >> 5;

    int beg = g_ptr[gw], deg = g_deg[gw];
    float4 ad = g_ad1[gw];

    float4 acc = make_float4(0.f, 0.f, 0.f, 0.f);
    float4 dsl = make_float4(0.f, 0.f, 0.f, 0.f);
    int head = lane >> 3;

    for (int base = 0; base < deg; base += 32) {
        int cnt = min(32, deg - base);
        if (lane < cnt) {
            int s = g_esrc[beg + base + lane];
            s_src[wb][lane] = s;
            float4 a = g_as1[s];
            float4 ev;
            ev.x = __expf(lrelu(a.x + ad.x));
            ev.y = __expf(lrelu(a.y + ad.y));
            ev.z = __expf(lrelu(a.z + ad.z));
            ev.w = __expf(lrelu(a.w + ad.w));
            s_al[wb][lane] = ev;
            dsl.x += ev.x; dsl.y += ev.y; dsl.z += ev.z; dsl.w += ev.w;
        }
        __syncwarp();
#pragma unroll 4
        for (int j = 0; j < cnt; j++) {
            int s = s_src[wb][j];
            float ev = ((float*)&s_al[wb][j])[head];
            uint2 hv = g_h1[s * 32 + lane];
            float2 lo = __half22float2(*(__half2*)&hv.x);
            float2 hi = __half22float2(*(__half2*)&hv.y);
            acc.x += lo.x * ev;
            acc.y += lo.y * ev;
            acc.z += hi.x * ev;
            acc.w += hi.y * ev;
        }
        __syncwarp();
    }

#pragma unroll
    for (int o = 16; o; o >>= 1) {
        dsl.x += __shfl_xor_sync(0xffffffffu, dsl.x, o);
        dsl.y += __shfl_xor_sync(0xffffffffu, dsl.y, o);
        dsl.z += __shfl_xor_sync(0xffffffffu, dsl.z, o);
        dsl.w += __shfl_xor_sync(0xffffffffu, dsl.w, o);
    }
    float invh = __fdividef(1.f, ((float*)&dsl)[head]);
    acc.x *= invh; acc.y *= invh; acc.z *= invh; acc.w *= invh;
    g_acc1[gw * 32 + lane] = acc;
}

// ---------------- GEMM2: HMMA, 128 rows/block, N=48 (R10 version) ----------------
__global__ void __launch_bounds__(256) k_gemm2(const float* __restrict__ b1) {
    __shared__ __align__(16) __half As[128 * LDA];
    __shared__ __align__(16) __half Bs[16 * LDB2];
    int t = threadIdx.x, lane = t & 31, warp = t >> 5;
    int row0 = blockIdx.x * 128;

    for (int i = t; i < 128 * 32; i += 256) {
        int r = i >> 5, c4 = i & 31;
        int gr = min(row0 + r, NN - 1);
        float4 v = ((const float4*)(const float*)g_acc1)[gr * 32 + c4];
        float4 bv = ((const float4*)b1)[c4];
        *(__half2*)&As[r * LDA + c4 * 4]     = __floats2half2_rn(fmaxf(v.x + bv.x, 0.f), fmaxf(v.y + bv.y, 0.f));
        *(__half2*)&As[r * LDA + c4 * 4 + 2] = __floats2half2_rn(fmaxf(v.z + bv.z, 0.f), fmaxf(v.w + bv.w, 0.f));
    }

    float acc[6][4];
#pragma unroll
    for (int p = 0; p < 6; p++)
#pragma unroll
        for (int q = 0; q < 4; q++) acc[p][q] = 0.f;

    int wrow = warp * 16;
    uint32_t a_row_addr = smem_u32(&As[(wrow + (lane & 15)) * LDA + ((lane >> 4) * 8)]);
    uint32_t b_addr0 = (lane < 16) ? smem_u32(&Bs[(lane & 15) * LDB2])
                                   : smem_u32(&Bs[(lane - 16) * LDB2 + 8]);

    for (int kb = 0; kb < 8; kb++) {
        __syncthreads();
        if (t < 96) {
            int r = t / 6, c8 = t % 6;
            uint4 v = ((const uint4*)&g_W2h[(kb * 16 + r) * 48])[c8];
            *(uint4*)&Bs[r * LDB2 + c8 * 8] = v;
        }
        __syncthreads();

        uint32_t a0, a1, a2, a3;
        ldmatrix_x4(a0, a1, a2, a3, a_row_addr + kb * 32);

#pragma unroll
        for (int p = 0; p < 3; p++) {
            uint32_t b0, b1r, b2, b3;
            ldmatrix_x4_trans(b0, b1r, b2, b3, b_addr0 + p * 32);
            mma16816(acc[2 * p],     a0, a1, a2, a3, b0, b1r);
            mma16816(acc[2 * p + 1], a0, a1, a2, a3, b2, b3);
        }
    }
    __syncthreads();

    int g = lane >> 2, c0 = (lane & 3) * 2;
#pragma unroll
    for (int i = 0; i < 6; i++) {
        int cbase = (i >> 1) * 16 + (i & 1) * 8 + c0;
#pragma unroll
        for (int q = 0; q < 4; q++) {
            int col = cbase + (q & 1);
            int r = wrow + g + ((q < 2) ? 0 : 8);
            if (col < OD) {
                As[r * 48 + col] = __float2half_rn(acc[i][q]);
            } else if (col == OD) {
                int row = row0 + r;
                if (row < NN) g_as2[row] = acc[i][q];
            } else if (col == OD + 1) {
                int row = row0 + r;
                if (row < NN) g_ad2[row] = acc[i][q];
            }
        }
    }
    __syncthreads();
    for (int i = t; i < 128 * 5; i += 256) {
        int r = i / 5, c = i % 5;
        int row = row0 + r;
        if (row < NN) ((uint4*)g_h2)[row * 5 + c] = *(const uint4*)&As[r * 48 + c * 8];
    }
}

// ---------------- layer-2 aggregation (R10 version) ----------------
__global__ void __launch_bounds__(256) k_agg2(float* __restrict__ out,
                                              const float* __restrict__ b2) {
    __shared__ int   s_src[8][32];
    __shared__ float s_al[8][32];
    int gw = (blockIdx.x * 256 + threadIdx.x) >> 5;
    if (gw >= NN) return;
    int lane = threadIdx.x & 31;
    int wb = threadIdx.x >> 5;

    int beg = g_ptr[gw], deg = g_deg[gw];
    float ad = g_ad2[gw];

    const __half2* h2p = (const __half2*)g_h2;
    float2 acc = make_float2(0.f, 0.f);
    float dsl = 0.f;

    for (int base = 0; base < deg; base += 32) {
        int cnt = min(32, deg - base);
        if (lane < cnt) {
            int s = g_esrc[beg + base + lane];
            s_src[wb][lane] = s;
            float ev = __expf(lrelu(g_as2[s] + ad));
            s_al[wb][lane] = ev;
            dsl += ev;
        }
        __syncwarp();
        if (lane < 20) {
#pragma unroll 4
            for (int j = 0; j < cnt; j++) {
                int s = s_src[wb][j];
                float ev = s_al[wb][j];
                float2 h = __half22float2(h2p[s * 20 + lane]);
                acc.x += h.x * ev;
                acc.y += h.y * ev;
            }
        }
        __syncwarp();
    }

#pragma unroll
    for (int o = 16; o; o >>= 1) dsl += __shfl_xor_sync(0xffffffffu, dsl, o);
    float inv = __fdividef(1.f, dsl);

    if (lane < 20) {
        float2 bv = ((const float2*)b2)[lane];
        acc.x = acc.x * inv + bv.x;
        acc.y = acc.y * inv + bv.y;
        ((float2*)out)[gw * 20 + lane] = acc;
    }
}

// ---------------- launcher ----------------
extern "C" void kernel_launch(void* const* d_in, const int* in_sizes, int n_in,
                              void* d_out, int out_size)
{
    const float* x   = (const float*)d_in[0];
    const int*   ei  = (const int*)d_in[1];
    const float* W1  = (const float*)d_in[2];
    const float* as1 = (const float*)d_in[3];
    const float* ad1 = (const float*)d_in[4];
    const float* b1  = (const float*)d_in[5];
    const float* W2  = (const float*)d_in[6];
    const float* as2 = (const float*)d_in[7];
    const float* ad2 = (const float*)d_in[8];
    const float* b2  = (const float*)d_in[9];
    float* out = (float*)d_out;

    const int TB  = 256;
    const int WBK = (NN * 32 + TB - 1) / TB;

    k_prep<<<1, 128>>>(W1, as1, ad1, W2, as2, ad2);
    k_csr<<<CSRB, 1024>>>(ei);
    k_gemm1<<<(NN + 127) / 128, 256>>>(x);
    k_agg1<<<WBK, TB>>>();
    k_gemm2<<<(NN + 127) / 128, 256>>>(b1);
    k_agg2<<<WBK, TB>>>(out, b2);
}

// round 12
// speedup vs baseline: 1.1348x; 1.1348x over previous
#include <cuda_runtime.h>
#include <cuda_fp16.h>
#include <stdint.h>

#define NN    50000
#define NE    800000
#define ET    (NE + NN)      // 850000
#define OD    40
#define NEG_SLOPE 0.2f
#define NB    49             // ceil(NN/1024) scan blocks

#define LDA 136              // A smem row stride (halfs)
#define LDB 152              // gemm1 B smem row stride (halfs)
#define LDB2 56              // gemm2 B smem row stride (halfs)

// ---------------- scratch ----------------
__device__ __align__(16) __half g_W1h[128 * 144];  // [W1 | Va | Vd | pad] fp16
__device__ __align__(16) __half g_W2h[128 * 48];   // [W2 | ws | wd | pad] fp16
__device__ __align__(16) uint2  g_h1[NN * 32];     // [NN][128] fp16
__device__ __align__(16) float4 g_acc1[NN * 32];   // [NN][128] fp32 (normalized)
__device__ float4 g_as1[NN];
__device__ float4 g_ad1[NN];
__device__ __align__(16) __half g_h2[NN * OD];     // [NN][40] fp16
__device__ float  g_as2[NN];
__device__ float  g_ad2[NN];
// CSR
__device__ int    g_deg[NN];
__device__ int    g_incl[NN];
__device__ int    g_bsum[64];
__device__ int    g_ptr[NN];
__device__ int    g_eoff[ET];
__device__ int    g_esrc[ET];

// ---------------- helpers ----------------
__device__ __forceinline__ float lrelu(float v) { return v > 0.f ? v : NEG_SLOPE * v; }

__device__ __forceinline__ void edge_sd(const int* __restrict__ ei, int e, int& s, int& d) {
    if (e < NE) { s = ei[e]; d = ei[NE + e]; }
    else        { s = d = e - NE; }
}
__device__ __forceinline__ uint32_t smem_u32(const void* p) {
    return (uint32_t)__cvta_generic_to_shared(p);
}
__device__ __forceinline__ void ldmatrix_x4(uint32_t& r0, uint32_t& r1, uint32_t& r2, uint32_t& r3, uint32_t addr) {
    asm volatile("ldmatrix.sync.aligned.m8n8.x4.shared.b16 {%0,%1,%2,%3}, [%4];"
                 : "=r"(r0), "=r"(r1), "=r"(r2), "=r"(r3) : "r"(addr));
}
__device__ __forceinline__ void ldmatrix_x4_trans(uint32_t& r0, uint32_t& r1, uint32_t& r2, uint32_t& r3, uint32_t addr) {
    asm volatile("ldmatrix.sync.aligned.m8n8.x4.trans.shared.b16 {%0,%1,%2,%3}, [%4];"
                 : "=r"(r0), "=r"(r1), "=r"(r2), "=r"(r3) : "r"(addr));
}
__device__ __forceinline__ void mma16816(float* d, uint32_t a0, uint32_t a1, uint32_t a2, uint32_t a3,
                                         uint32_t b0, uint32_t b1) {
    asm volatile("mma.sync.aligned.m16n8k16.row.col.f32.f16.f16.f32 "
                 "{%0,%1,%2,%3}, {%4,%5,%6,%7}, {%8,%9}, {%0,%1,%2,%3};"
                 : "+f"(d[0]), "+f"(d[1]), "+f"(d[2]), "+f"(d[3])
                 : "r"(a0), "r"(a1), "r"(a2), "r"(a3), "r"(b0), "r"(b1));
}

// ---------------- init: zero deg + build W1h + W2h ----------------
__global__ void k_zero_prep(const float* __restrict__ W1,
                            const float* __restrict__ a1s, const float* __restrict__ a1d,
                            const float* __restrict__ W2,
                            const float* __restrict__ a2s, const float* __restrict__ a2d) {
    int i = blockIdx.x * blockDim.x + threadIdx.x;
    if (i < NN) g_deg[i] = 0;
    if (blockIdx.x == 0 && threadIdx.x < 128) {
        int k = threadIdx.x;
        __half* d2 = &g_W2h[k * 48];
        float ws = 0.f, wd = 0.f;
        for (int c = 0; c < OD; c++) {
            float w = W2[k * OD + c];
            d2[c] = __float2half_rn(w);
            ws += w * a2s[c];
            wd += w * a2d[c];
        }
        d2[40] = __float2half_rn(ws);
        d2[41] = __float2half_rn(wd);
#pragma unroll
        for (int c = 42; c < 48; c++) d2[c] = __float2half_rn(0.f);
    }
    if (blockIdx.x == 1 && threadIdx.x < 128) {
        int k = threadIdx.x;
        __half* dst = &g_W1h[k * 144];
        float va[4] = {0.f, 0.f, 0.f, 0.f}, vd[4] = {0.f, 0.f, 0.f, 0.f};
        for (int c = 0; c < 128; c++) {
            float w = W1[k * 128 + c];
            dst[c] = __float2half_rn(w);
            int h = c >> 5;
            va[h] += w * a1s[c];
            vd[h] += w * a1d[c];
        }
#pragma unroll
        for (int h = 0; h < 4; h++) {
            dst[128 + h] = __float2half_rn(va[h]);
            dst[132 + h] = __float2half_rn(vd[h]);
        }
#pragma unroll
        for (int c = 136; c < 144; c++) dst[c] = __float2half_rn(0.f);
    }
}

// ---------------- GEMM1: HMMA, 128 rows/block, N=136, + fused histogram ----------------
__global__ void __launch_bounds__(256) k_gemm1(const float* __restrict__ x,
                                               const int* __restrict__ ei) {
    __shared__ __align__(16) __half As[128 * LDA];
    __shared__ __align__(16) __half Bs[16 * LDB];
    int t = threadIdx.x, lane = t & 31, warp = t >> 5;
    int row0 = blockIdx.x * 128;

    // fused histogram slice — hides under tensor-core work of other warps/blocks
    {
        const int S = (ET + gridDim.x - 1) / gridDim.x;
        int e0 = blockIdx.x * S;
        int e1 = min(ET, e0 + S);
        for (int e = e0 + t; e < e1; e += 256) {
            int d = (e < NE) ? ei[NE + e] : (e - NE);
            g_eoff[e] = atomicAdd(&g_deg[d], 1);
        }
    }

    for (int i = t; i < 128 * 32; i += 256) {
        int r = i >> 5, c4 = i & 31;
        int gr = min(row0 + r, NN - 1);
        float4 v = ((const float4*)x)[gr * 32 + c4];
        *(__half2*)&As[r * LDA + c4 * 4]     = __floats2half2_rn(v.x, v.y);
        *(__half2*)&As[r * LDA + c4 * 4 + 2] = __floats2half2_rn(v.z, v.w);
    }

    float acc[17][4];
#pragma unroll
    for (int p = 0; p < 17; p++)
#pragma unroll
        for (int q = 0; q < 4; q++) acc[p][q] = 0.f;

    int wrow = warp * 16;
    uint32_t a_row_addr = smem_u32(&As[(wrow + (lane & 15)) * LDA + ((lane >> 4) * 8)]);
    uint32_t b_addr0 = (lane < 16) ? smem_u32(&Bs[(lane & 15) * LDB])
                                   : smem_u32(&Bs[(lane - 16) * LDB + 8]);

    for (int kb = 0; kb < 8; kb++) {
        __syncthreads();
        for (int i = t; i < 288; i += 256) {
            int r = i / 18, c8 = i % 18;
            uint4 v = ((const uint4*)&g_W1h[(kb * 16 + r) * 144])[c8];
            *(uint4*)&Bs[r * LDB + c8 * 8] = v;
        }
        __syncthreads();

        uint32_t a0, a1, a2, a3;
        ldmatrix_x4(a0, a1, a2, a3, a_row_addr + kb * 32);

#pragma unroll
        for (int p = 0; p < 9; p++) {
            uint32_t b0, b1, b2, b3;
            ldmatrix_x4_trans(b0, b1, b2, b3, b_addr0 + p * 32);
            mma16816(acc[2 * p], a0, a1, a2, a3, b0, b1);
            if (p < 8) mma16816(acc[2 * p + 1], a0, a1, a2, a3, b2, b3);
        }
    }
    __syncthreads();

    int g = lane >> 2, c0 = (lane & 3) * 2;
    {
        int r_lo = row0 + wrow + g, r_hi = r_lo + 8;
#pragma unroll
        for (int q = 0; q < 4; q++) {
            int row = (q < 2) ? r_lo : r_hi;
            int c = c0 + (q & 1);
            if (row < NN) {
                if (c < 4) ((float*)&g_as1[row])[c] = acc[16][q];
                else       ((float*)&g_ad1[row])[c - 4] = acc[16][q];
            }
        }
    }

#pragma unroll
    for (int tl = 0; tl < 16; tl++) {
        *(__half2*)&As[(wrow + g) * LDA + tl * 8 + c0]     = __floats2half2_rn(acc[tl][0], acc[tl][1]);
        *(__half2*)&As[(wrow + g + 8) * LDA + tl * 8 + c0] = __floats2half2_rn(acc[tl][2], acc[tl][3]);
    }
    __syncthreads();
    for (int i = t; i < 128 * 16; i += 256) {
        int r = i >> 4, c16 = i & 15;
        int row = row0 + r;
        if (row < NN) ((uint4*)g_h1)[row * 16 + c16] = *(const uint4*)&As[r * LDA + c16 * 8];
    }
}

// ---------------- CSR scan (R10 two-kernel version) ----------------
__global__ void __launch_bounds__(1024) k_scanA() {
    __shared__ int wsum[32];
    int t = threadIdx.x, lane = t & 31, wid = t >> 5;
    int i = blockIdx.x * 1024 + t;
    int v = (i < NN) ? g_deg[i] : 0;
    int s = v;
#pragma unroll
    for (int o = 1; o < 32; o <<= 1) {
        int n = __shfl_up_sync(0xffffffffu, s, o);
        if (lane >= o) s += n;
    }
    if (lane == 31) wsum[wid] = s;
    __syncthreads();
    if (wid == 0) {
        int ws = wsum[lane];
#pragma unroll
        for (int o = 1; o < 32; o <<= 1) {
            int n = __shfl_up_sync(0xffffffffu, ws, o);
            if (lane >= o) ws += n;
        }
        wsum[lane] = ws;
    }
    __syncthreads();
    int res = s + (wid ? wsum[wid - 1] : 0);
    if (i < NN) g_incl[i] = res;
    if (t == 1023) g_bsum[blockIdx.x] = res;
}

__global__ void __launch_bounds__(256) k_scanBC() {
    __shared__ int s_bscan[64];
    int t = threadIdx.x;
    if (t < 32) {
        int lane = t;
        int a = (lane < NB) ? g_bsum[lane] : 0;
#pragma unroll
        for (int o = 1; o < 32; o <<= 1) {
            int n = __shfl_up_sync(0xffffffffu, a, o);
            if (lane >= o) a += n;
        }
        int tot = __shfl_sync(0xffffffffu, a, 31);
        int b = (32 + lane < NB) ? g_bsum[32 + lane] : 0;
#pragma unroll
        for (int o = 1; o < 32; o <<= 1) {
            int n = __shfl_up_sync(0xffffffffu, b, o);
            if (lane >= o) b += n;
        }
        s_bscan[lane] = a;
        s_bscan[32 + lane] = b + tot;
    }
    __syncthreads();
    int i = blockIdx.x * 256 + t;
    if (i >= NN) return;
    int b = i >> 10;
    g_ptr[i] = g_incl[i] - g_deg[i] + (b ? s_bscan[b - 1] : 0);
}

__global__ void k_fill(const int* __restrict__ ei) {
    int e = blockIdx.x * blockDim.x + threadIdx.x;
    if (e >= ET) return;
    int s, d; edge_sd(ei, e, s, d);
    g_esrc[g_ptr[d] + g_eoff[e]] = s;
}

// ---------------- layer-1 aggregation (R10 logic, forced 8 blocks/SM) ----------------
__global__ void __launch_bounds__(256, 8) k_agg1() {
    __shared__ int    s_src[8][32];
    __shared__ float4 s_al[8][32];
    int gw = (blockIdx.x * 256 + threadIdx.x) >> 5;
    if (gw >= NN) return;
    int lane = threadIdx.x & 31;
    int wb = threadIdx.x >> 5;

    int beg = g_ptr[gw], deg = g_deg[gw];
    float4 ad = g_ad1[gw];

    float4 acc = make_float4(0.f, 0.f, 0.f, 0.f);
    float4 dsl = make_float4(0.f, 0.f, 0.f, 0.f);
    int head = lane >> 3;

    for (int base = 0; base < deg; base += 32) {
        int cnt = min(32, deg - base);
        if (lane < cnt) {
            int s = g_esrc[beg + base + lane];
            s_src[wb][lane] = s;
            float4 a = g_as1[s];
            float4 ev;
            ev.x = __expf(lrelu(a.x + ad.x));
            ev.y = __expf(lrelu(a.y + ad.y));
            ev.z = __expf(lrelu(a.z + ad.z));
            ev.w = __expf(lrelu(a.w + ad.w));
            s_al[wb][lane] = ev;
            dsl.x += ev.x; dsl.y += ev.y; dsl.z += ev.z; dsl.w += ev.w;
        }
        __syncwarp();
#pragma unroll 4
        for (int j = 0; j < cnt; j++) {
            int s = s_src[wb][j];
            float ev = ((float*)&s_al[wb][j])[head];
            uint2 hv = g_h1[s * 32 + lane];
            float2 lo = __half22float2(*(__half2*)&hv.x);
            float2 hi = __half22float2(*(__half2*)&hv.y);
            acc.x += lo.x * ev;
            acc.y += lo.y * ev;
            acc.z += hi.x * ev;
            acc.w += hi.y * ev;
        }
        __syncwarp();
    }

#pragma unroll
    for (int o = 16; o; o >>= 1) {
        dsl.x += __shfl_xor_sync(0xffffffffu, dsl.x, o);
        dsl.y += __shfl_xor_sync(0xffffffffu, dsl.y, o);
        dsl.z += __shfl_xor_sync(0xffffffffu, dsl.z, o);
        dsl.w += __shfl_xor_sync(0xffffffffu, dsl.w, o);
    }
    float invh = __fdividef(1.f, ((float*)&dsl)[head]);
    acc.x *= invh; acc.y *= invh; acc.z *= invh; acc.w *= invh;
    g_acc1[gw * 32 + lane] = acc;
}

// ---------------- GEMM2: HMMA, 128 rows/block, N=48 (R10 version) ----------------
__global__ void __launch_bounds__(256) k_gemm2(const float* __restrict__ b1) {
    __shared__ __align__(16) __half As[128 * LDA];
    __shared__ __align__(16) __half Bs[16 * LDB2];
    int t = threadIdx.x, lane = t & 31, warp = t >> 5;
    int row0 = blockIdx.x * 128;

    for (int i = t; i < 128 * 32; i += 256) {
        int r = i >> 5, c4 = i & 31;
        int gr = min(row0 + r, NN - 1);
        float4 v = ((const float4*)(const float*)g_acc1)[gr * 32 + c4];
        float4 bv = ((const float4*)b1)[c4];
        *(__half2*)&As[r * LDA + c4 * 4]     = __floats2half2_rn(fmaxf(v.x + bv.x, 0.f), fmaxf(v.y + bv.y, 0.f));
        *(__half2*)&As[r * LDA + c4 * 4 + 2] = __floats2half2_rn(fmaxf(v.z + bv.z, 0.f), fmaxf(v.w + bv.w, 0.f));
    }

    float acc[6][4];
#pragma unroll
    for (int p = 0; p < 6; p++)
#pragma unroll
        for (int q = 0; q < 4; q++) acc[p][q] = 0.f;

    int wrow = warp * 16;
    uint32_t a_row_addr = smem_u32(&As[(wrow + (lane & 15)) * LDA + ((lane >> 4) * 8)]);
    uint32_t b_addr0 = (lane < 16) ? smem_u32(&Bs[(lane & 15) * LDB2])
                                   : smem_u32(&Bs[(lane - 16) * LDB2 + 8]);

    for (int kb = 0; kb < 8; kb++) {
        __syncthreads();
        if (t < 96) {
            int r = t / 6, c8 = t % 6;
            uint4 v = ((const uint4*)&g_W2h[(kb * 16 + r) * 48])[c8];
            *(uint4*)&Bs[r * LDB2 + c8 * 8] = v;
        }
        __syncthreads();

        uint32_t a0, a1, a2, a3;
        ldmatrix_x4(a0, a1, a2, a3, a_row_addr + kb * 32);

#pragma unroll
        for (int p = 0; p < 3; p++) {
            uint32_t b0, b1r, b2, b3;
            ldmatrix_x4_trans(b0, b1r, b2, b3, b_addr0 + p * 32);
            mma16816(acc[2 * p],     a0, a1, a2, a3, b0, b1r);
            mma16816(acc[2 * p + 1], a0, a1, a2, a3, b2, b3);
        }
    }
    __syncthreads();

    int g = lane >> 2, c0 = (lane & 3) * 2;
#pragma unroll
    for (int i = 0; i < 6; i++) {
        int cbase = (i >> 1) * 16 + (i & 1) * 8 + c0;
#pragma unroll
        for (int q = 0; q < 4; q++) {
            int col = cbase + (q & 1);
            int r = wrow + g + ((q < 2) ? 0 : 8);
            if (col < OD) {
                As[r * 48 + col] = __float2half_rn(acc[i][q]);
            } else if (col == OD) {
                int row = row0 + r;
                if (row < NN) g_as2[row] = acc[i][q];
            } else if (col == OD + 1) {
                int row = row0 + r;
                if (row < NN) g_ad2[row] = acc[i][q];
            }
        }
    }
    __syncthreads();
    for (int i = t; i < 128 * 5; i += 256) {
        int r = i / 5, c = i % 5;
        int row = row0 + r;
        if (row < NN) ((uint4*)g_h2)[row * 5 + c] = *(const uint4*)&As[r * 48 + c * 8];
    }
}

// ---------------- layer-2 aggregation (R10 version) ----------------
__global__ void __launch_bounds__(256) k_agg2(float* __restrict__ out,
                                              const float* __restrict__ b2) {
    __shared__ int   s_src[8][32];
    __shared__ float s_al[8][32];
    int gw = (blockIdx.x * 256 + threadIdx.x) >> 5;
    if (gw >= NN) return;
    int lane = threadIdx.x & 31;
    int wb = threadIdx.x >> 5;

    int beg = g_ptr[gw], deg = g_deg[gw];
    float ad = g_ad2[gw];

    const __half2* h2p = (const __half2*)g_h2;
    float2 acc = make_float2(0.f, 0.f);
    float dsl = 0.f;

    for (int base = 0; base < deg; base += 32) {
        int cnt = min(32, deg - base);
        if (lane < cnt) {
            int s = g_esrc[beg + base + lane];
            s_src[wb][lane] = s;
            float ev = __expf(lrelu(g_as2[s] + ad));
            s_al[wb][lane] = ev;
            dsl += ev;
        }
        __syncwarp();
        if (lane < 20) {
#pragma unroll 4
            for (int j = 0; j < cnt; j++) {
                int s = s_src[wb][j];
                float ev = s_al[wb][j];
                float2 h = __half22float2(h2p[s * 20 + lane]);
                acc.x += h.x * ev;
                acc.y += h.y * ev;
            }
        }
        __syncwarp();
    }

#pragma unroll
    for (int o = 16; o; o >>= 1) dsl += __shfl_xor_sync(0xffffffffu, dsl, o);
    float inv = __fdividef(1.f, dsl);

    if (lane < 20) {
        float2 bv = ((const float2*)b2)[lane];
        acc.x = acc.x * inv + bv.x;
        acc.y = acc.y * inv + bv.y;
        ((float2*)out)[gw * 20 + lane] = acc;
    }
}

// ---------------- launcher ----------------
extern "C" void kernel_launch(void* const* d_in, const int* in_sizes, int n_in,
                              void* d_out, int out_size)
{
    const float* x   = (const float*)d_in[0];
    const int*   ei  = (const int*)d_in[1];
    const float* W1  = (const float*)d_in[2];
    const float* as1 = (const float*)d_in[3];
    const float* ad1 = (const float*)d_in[4];
    const float* b1  = (const float*)d_in[5];
    const float* W2  = (const float*)d_in[6];
    const float* as2 = (const float*)d_in[7];
    const float* ad2 = (const float*)d_in[8];
    const float* b2  = (const float*)d_in[9];
    float* out = (float*)d_out;

    const int TB  = 256;
    const int EB  = (ET + TB - 1) / TB;
    const int NBK = (NN + TB - 1) / TB;
    const int WBK = (NN * 32 + TB - 1) / TB;

    k_zero_prep<<<NBK, TB>>>(W1, as1, ad1, W2, as2, ad2);
    k_gemm1<<<(NN + 127) / 128, 256>>>(x, ei);
    k_scanA<<<NB, 1024>>>();
    k_scanBC<<<NBK, TB>>>();
    k_fill<<<EB, TB>>>(ei);
    k_agg1<<<WBK, TB>>>();
    k_gemm2<<<(NN + 127) / 128, 256>>>(b1);
    k_agg2<<<WBK, TB>>>(out, b2);
}

// round 17
// speedup vs baseline: 1.2460x; 1.0980x over previous
#include <cuda_runtime.h>
#include <cuda_fp16.h>
#include <stdint.h>

#define NN    50000
#define NE    800000
#define ET    (NE + NN)      // 850000
#define OD    40
#define NEG_SLOPE 0.2f
#define NB    49             // ceil(NN/1024) scan blocks

#define LDA 136              // A smem row stride (halfs)
#define LDB 152              // gemm1 B smem row stride (halfs)
#define LDB2 56              // gemm2 B smem row stride (halfs)

// ---------------- scratch ----------------
__device__ __align__(16) __half g_W1h[128 * 144];  // [W1 | Va | Vd | pad] fp16
__device__ __align__(16) __half g_W2h[128 * 48];   // [W2 | ws | wd | pad] fp16
__device__ __align__(16) uint2  g_h1[NN * 32];     // [NN][128] fp16
__device__ __align__(16) uint2  g_acc1h[NN * 32];  // [NN][128] fp16: relu(agg + b1)
__device__ float4 g_as1[NN];
__device__ float4 g_ad1[NN];
__device__ __align__(16) __half g_h2[NN * OD];     // [NN][40] fp16
__device__ float  g_as2[NN];
__device__ float  g_ad2[NN];
// CSR
__device__ int    g_deg[NN];
__device__ int    g_incl[NN];
__device__ int    g_bsum[64];
__device__ int    g_ptr[NN];
__device__ int    g_eoff[ET];
__device__ int    g_esrc[ET];

// ---------------- helpers ----------------
__device__ __forceinline__ float lrelu(float v) { return v > 0.f ? v : NEG_SLOPE * v; }

__device__ __forceinline__ void edge_sd(const int* __restrict__ ei, int e, int& s, int& d) {
    if (e < NE) { s = ei[e]; d = ei[NE + e]; }
    else        { s = d = e - NE; }
}
__device__ __forceinline__ uint32_t smem_u32(const void* p) {
    return (uint32_t)__cvta_generic_to_shared(p);
}
__device__ __forceinline__ void ldmatrix_x4(uint32_t& r0, uint32_t& r1, uint32_t& r2, uint32_t& r3, uint32_t addr) {
    asm volatile("ldmatrix.sync.aligned.m8n8.x4.shared.b16 {%0,%1,%2,%3}, [%4];"
                 : "=r"(r0), "=r"(r1), "=r"(r2), "=r"(r3) : "r"(addr));
}
__device__ __forceinline__ void ldmatrix_x4_trans(uint32_t& r0, uint32_t& r1, uint32_t& r2, uint32_t& r3, uint32_t addr) {
    asm volatile("ldmatrix.sync.aligned.m8n8.x4.trans.shared.b16 {%0,%1,%2,%3}, [%4];"
                 : "=r"(r0), "=r"(r1), "=r"(r2), "=r"(r3) : "r"(addr));
}
__device__ __forceinline__ void mma16816(float* d, uint32_t a0, uint32_t a1, uint32_t a2, uint32_t a3,
                                         uint32_t b0, uint32_t b1) {
    asm volatile("mma.sync.aligned.m16n8k16.row.col.f32.f16.f16.f32 "
                 "{%0,%1,%2,%3}, {%4,%5,%6,%7}, {%8,%9}, {%0,%1,%2,%3};"
                 : "+f"(d[0]), "+f"(d[1]), "+f"(d[2]), "+f"(d[3])
                 : "r"(a0), "r"(a1), "r"(a2), "r"(a3), "r"(b0), "r"(b1));
}

// ---------------- init: zero deg + build W1h + W2h ----------------
__global__ void k_zero_prep(const float* __restrict__ W1,
                            const float* __restrict__ a1s, const float* __restrict__ a1d,
                            const float* __restrict__ W2,
                            const float* __restrict__ a2s, const float* __restrict__ a2d) {
    int i = blockIdx.x * blockDim.x + threadIdx.x;
    if (i < NN) g_deg[i] = 0;
    if (blockIdx.x == 0 && threadIdx.x < 128) {
        int k = threadIdx.x;
        __half* d2 = &g_W2h[k * 48];
        float ws = 0.f, wd = 0.f;
        for (int c = 0; c < OD; c++) {
            float w = W2[k * OD + c];
            d2[c] = __float2half_rn(w);
            ws += w * a2s[c];
            wd += w * a2d[c];
        }
        d2[40] = __float2half_rn(ws);
        d2[41] = __float2half_rn(wd);
#pragma unroll
        for (int c = 42; c < 48; c++) d2[c] = __float2half_rn(0.f);
    }
    if (blockIdx.x == 1 && threadIdx.x < 128) {
        int k = threadIdx.x;
        __half* dst = &g_W1h[k * 144];
        float va[4] = {0.f, 0.f, 0.f, 0.f}, vd[4] = {0.f, 0.f, 0.f, 0.f};
        for (int c = 0; c < 128; c++) {
            float w = W1[k * 128 + c];
            dst[c] = __float2half_rn(w);
            int h = c >> 5;
            va[h] += w * a1s[c];
            vd[h] += w * a1d[c];
        }
#pragma unroll
        for (int h = 0; h < 4; h++) {
            dst[128 + h] = __float2half_rn(va[h]);
            dst[132 + h] = __float2half_rn(vd[h]);
        }
#pragma unroll
        for (int c = 136; c < 144; c++) dst[c] = __float2half_rn(0.f);
    }
}

// histogram + per-edge within-node offset
__global__ void k_hist(const int* __restrict__ ei) {
    int e = blockIdx.x * blockDim.x + threadIdx.x;
    if (e >= ET) return;
    int d = (e < NE) ? ei[NE + e] : (e - NE);
    g_eoff[e] = atomicAdd(&g_deg[d], 1);
}

// ---------------- GEMM1: HMMA, 128 rows/block, N=136 ----------------
__global__ void __launch_bounds__(256) k_gemm1(const float* __restrict__ x) {
    __shared__ __align__(16) __half As[128 * LDA];
    __shared__ __align__(16) __half Bs[16 * LDB];
    int t = threadIdx.x, lane = t & 31, warp = t >> 5;
    int row0 = blockIdx.x * 128;

    for (int i = t; i < 128 * 32; i += 256) {
        int r = i >> 5, c4 = i & 31;
        int gr = min(row0 + r, NN - 1);
        float4 v = ((const float4*)x)[gr * 32 + c4];
        *(__half2*)&As[r * LDA + c4 * 4]     = __floats2half2_rn(v.x, v.y);
        *(__half2*)&As[r * LDA + c4 * 4 + 2] = __floats2half2_rn(v.z, v.w);
    }

    float acc[17][4];
#pragma unroll
    for (int p = 0; p < 17; p++)
#pragma unroll
        for (int q = 0; q < 4; q++) acc[p][q] = 0.f;

    int wrow = warp * 16;
    uint32_t a_row_addr = smem_u32(&As[(wrow + (lane & 15)) * LDA + ((lane >> 4) * 8)]);
    uint32_t b_addr0 = (lane < 16) ? smem_u32(&Bs[(lane & 15) * LDB])
                                   : smem_u32(&Bs[(lane - 16) * LDB + 8]);

    for (int kb = 0; kb < 8; kb++) {
        __syncthreads();
        for (int i = t; i < 288; i += 256) {
            int r = i / 18, c8 = i % 18;
            uint4 v = ((const uint4*)&g_W1h[(kb * 16 + r) * 144])[c8];
            *(uint4*)&Bs[r * LDB + c8 * 8] = v;
        }
        __syncthreads();

        uint32_t a0, a1, a2, a3;
        ldmatrix_x4(a0, a1, a2, a3, a_row_addr + kb * 32);

#pragma unroll
        for (int p = 0; p < 9; p++) {
            uint32_t b0, b1, b2, b3;
            ldmatrix_x4_trans(b0, b1, b2, b3, b_addr0 + p * 32);
            mma16816(acc[2 * p], a0, a1, a2, a3, b0, b1);
            if (p < 8) mma16816(acc[2 * p + 1], a0, a1, a2, a3, b2, b3);
        }
    }
    __syncthreads();

    int g = lane >> 2, c0 = (lane & 3) * 2;
    {
        int r_lo = row0 + wrow + g, r_hi = r_lo + 8;
#pragma unroll
        for (int q = 0; q < 4; q++) {
            int row = (q < 2) ? r_lo : r_hi;
            int c = c0 + (q & 1);
            if (row < NN) {
                if (c < 4) ((float*)&g_as1[row])[c] = acc[16][q];
                else       ((float*)&g_ad1[row])[c - 4] = acc[16][q];
            }
        }
    }

#pragma unroll
    for (int tl = 0; tl < 16; tl++) {
        *(__half2*)&As[(wrow + g) * LDA + tl * 8 + c0]     = __floats2half2_rn(acc[tl][0], acc[tl][1]);
        *(__half2*)&As[(wrow + g + 8) * LDA + tl * 8 + c0] = __floats2half2_rn(acc[tl][2], acc[tl][3]);
    }
    __syncthreads();
    for (int i = t; i < 128 * 16; i += 256) {
        int r = i >> 4, c16 = i & 15;
        int row = row0 + r;
        if (row < NN) ((uint4*)g_h1)[row * 16 + c16] = *(const uint4*)&As[r * LDA + c16 * 8];
    }
}

// ---------------- CSR scan ----------------
__global__ void __launch_bounds__(1024) k_scanA() {
    __shared__ int wsum[32];
    int t = threadIdx.x, lane = t & 31, wid = t >> 5;
    int i = blockIdx.x * 1024 + t;
    int v = (i < NN) ? g_deg[i] : 0;
    int s = v;
#pragma unroll
    for (int o = 1; o < 32; o <<= 1) {
        int n = __shfl_up_sync(0xffffffffu, s, o);
        if (lane >= o) s += n;
    }
    if (lane == 31) wsum[wid] = s;
    __syncthreads();
    if (wid == 0) {
        int ws = wsum[lane];
#pragma unroll
        for (int o = 1; o < 32; o <<= 1) {
            int n = __shfl_up_sync(0xffffffffu, ws, o);
            if (lane >= o) ws += n;
        }
        wsum[lane] = ws;
    }
    __syncthreads();
    int res = s + (wid ? wsum[wid - 1] : 0);
    if (i < NN) g_incl[i] = res;
    if (t == 1023) g_bsum[blockIdx.x] = res;
}

__global__ void __launch_bounds__(256) k_scanBC() {
    __shared__ int s_bscan[64];
    int t = threadIdx.x;
    if (t < 32) {
        int lane = t;
        int a = (lane < NB) ? g_bsum[lane] : 0;
#pragma unroll
        for (int o = 1; o < 32; o <<= 1) {
            int n = __shfl_up_sync(0xffffffffu, a, o);
            if (lane >= o) a += n;
        }
        int tot = __shfl_sync(0xffffffffu, a, 31);
        int b = (32 + lane < NB) ? g_bsum[32 + lane] : 0;
#pragma unroll
        for (int o = 1; o < 32; o <<= 1) {
            int n = __shfl_up_sync(0xffffffffu, b, o);
            if (lane >= o) b += n;
        }
        s_bscan[lane] = a;
        s_bscan[32 + lane] = b + tot;
    }
    __syncthreads();
    int i = blockIdx.x * 256 + t;
    if (i >= NN) return;
    int b = i >> 10;
    g_ptr[i] = g_incl[i] - g_deg[i] + (b ? s_bscan[b - 1] : 0);
}

__global__ void k_fill(const int* __restrict__ ei) {
    int e = blockIdx.x * blockDim.x + threadIdx.x;
    if (e >= ET) return;
    int s, d; edge_sd(ei, e, s, d);
    g_esrc[g_ptr[d] + g_eoff[e]] = s;
}

// ---------------- layer-1 aggregation: fused +b1, relu, fp16 store ----------------
__global__ void __launch_bounds__(256) k_agg1(const float* __restrict__ b1) {
    __shared__ int    s_src[8][32];
    __shared__ float4 s_al[8][32];
    int gw = (blockIdx.x * 256 + threadIdx.x) >> 5;
    if (gw >= NN) return;
    int lane = threadIdx.x & 31;
    int wb = threadIdx.x >> 5;

    int beg = g_ptr[gw], deg = g_deg[gw];
    float4 ad = g_ad1[gw];

    float4 acc = make_float4(0.f, 0.f, 0.f, 0.f);
    float4 dsl = make_float4(0.f, 0.f, 0.f, 0.f);
    int head = lane >> 3;

    for (int base = 0; base < deg; base += 32) {
        int cnt = min(32, deg - base);
        if (lane < cnt) {
            int s = g_esrc[beg + base + lane];
            s_src[wb][lane] = s;
            float4 a = g_as1[s];
            float4 ev;
            ev.x = __expf(lrelu(a.x + ad.x));
            ev.y = __expf(lrelu(a.y + ad.y));
            ev.z = __expf(lrelu(a.z + ad.z));
            ev.w = __expf(lrelu(a.w + ad.w));
            s_al[wb][lane] = ev;
            dsl.x += ev.x; dsl.y += ev.y; dsl.z += ev.z; dsl.w += ev.w;
        }
        __syncwarp();
#pragma unroll 4
        for (int j = 0; j < cnt; j++) {
            int s = s_src[wb][j];
            float ev = ((float*)&s_al[wb][j])[head];
            uint2 hv = g_h1[s * 32 + lane];
            float2 lo = __half22float2(*(__half2*)&hv.x);
            float2 hi = __half22float2(*(__half2*)&hv.y);
            acc.x += lo.x * ev;
            acc.y += lo.y * ev;
            acc.z += hi.x * ev;
            acc.w += hi.y * ev;
        }
        __syncwarp();
    }

#pragma unroll
    for (int o = 16; o; o >>= 1) {
        dsl.x += __shfl_xor_sync(0xffffffffu, dsl.x, o);
        dsl.y += __shfl_xor_sync(0xffffffffu, dsl.y, o);
        dsl.z += __shfl_xor_sync(0xffffffffu, dsl.z, o);
        dsl.w += __shfl_xor_sync(0xffffffffu, dsl.w, o);
    }
    float invh = __fdividef(1.f, ((float*)&dsl)[head]);

    // epilogue: normalize, +b1, relu, quantize fp16 (same logical point gemm2 quantized before)
    float4 bv = ((const float4*)b1)[lane];
    float r0 = fmaxf(acc.x * invh + bv.x, 0.f);
    float r1 = fmaxf(acc.y * invh + bv.y, 0.f);
    float r2 = fmaxf(acc.z * invh + bv.z, 0.f);
    float r3 = fmaxf(acc.w * invh + bv.w, 0.f);
    __half2 h01 = __floats2half2_rn(r0, r1);
    __half2 h23 = __floats2half2_rn(r2, r3);
    uint2 hv;
    hv.x = *(unsigned*)&h01;
    hv.y = *(unsigned*)&h23;
    g_acc1h[gw * 32 + lane] = hv;
}

// ---------------- GEMM2: HMMA, 128 rows/block, N=48; A = fp16 acc1h (direct copy) ----------------
__global__ void __launch_bounds__(256) k_gemm2() {
    __shared__ __align__(16) __half As[128 * LDA];
    __shared__ __align__(16) __half Bs[16 * LDB2];
    int t = threadIdx.x, lane = t & 31, warp = t >> 5;
    int row0 = blockIdx.x * 128;

    // stage A: straight uint4 copy of fp16 rows
    for (int i = t; i < 128 * 16; i += 256) {
        int r = i >> 4, c16 = i & 15;
        int gr = min(row0 + r, NN - 1);
        uint4 v = ((const uint4*)g_acc1h)[gr * 16 + c16];
        *(uint4*)&As[r * LDA + c16 * 8] = v;
    }

    float acc[6][4];
#pragma unroll
    for (int p = 0; p < 6; p++)
#pragma unroll
        for (int q = 0; q < 4; q++) acc[p][q] = 0.f;

    int wrow = warp * 16;
    uint32_t a_row_addr = smem_u32(&As[(wrow + (lane & 15)) * LDA + ((lane >> 4) * 8)]);
    uint32_t b_addr0 = (lane < 16) ? smem_u32(&Bs[(lane & 15) * LDB2])
                                   : smem_u32(&Bs[(lane - 16) * LDB2 + 8]);

    for (int kb = 0; kb < 8; kb++) {
        __syncthreads();
        if (t < 96) {
            int r = t / 6, c8 = t % 6;
            uint4 v = ((const uint4*)&g_W2h[(kb * 16 + r) * 48])[c8];
            *(uint4*)&Bs[r * LDB2 + c8 * 8] = v;
        }
        __syncthreads();

        uint32_t a0, a1, a2, a3;
        ldmatrix_x4(a0, a1, a2, a3, a_row_addr + kb * 32);

#pragma unroll
        for (int p = 0; p < 3; p++) {
            uint32_t b0, b1r, b2, b3;
            ldmatrix_x4_trans(b0, b1r, b2, b3, b_addr0 + p * 32);
            mma16816(acc[2 * p],     a0, a1, a2, a3, b0, b1r);
            mma16816(acc[2 * p + 1], a0, a1, a2, a3, b2, b3);
        }
    }
    __syncthreads();

    int g = lane >> 2, c0 = (lane & 3) * 2;
#pragma unroll
    for (int i = 0; i < 6; i++) {
        int cbase = (i >> 1) * 16 + (i & 1) * 8 + c0;
#pragma unroll
        for (int q = 0; q < 4; q++) {
            int col = cbase + (q & 1);
            int r = wrow + g + ((q < 2) ? 0 : 8);
            if (col < OD) {
                As[r * 48 + col] = __float2half_rn(acc[i][q]);
            } else if (col == OD) {
                int row = row0 + r;
                if (row < NN) g_as2[row] = acc[i][q];
            } else if (col == OD + 1) {
                int row = row0 + r;
                if (row < NN) g_ad2[row] = acc[i][q];
            }
        }
    }
    __syncthreads();
    for (int i = t; i < 128 * 5; i += 256) {
        int r = i / 5, c = i % 5;
        int row = row0 + r;
        if (row < NN) ((uint4*)g_h2)[row * 5 + c] = *(const uint4*)&As[r * 48 + c * 8];
    }
}

// ---------------- layer-2 aggregation (R10 version) ----------------
__global__ void __launch_bounds__(256) k_agg2(float* __restrict__ out,
                                              const float* __restrict__ b2) {
    __shared__ int   s_src[8][32];
    __shared__ float s_al[8][32];
    int gw = (blockIdx.x * 256 + threadIdx.x) >> 5;
    if (gw >= NN) return;
    int lane = threadIdx.x & 31;
    int wb = threadIdx.x >> 5;

    int beg = g_ptr[gw], deg = g_deg[gw];
    float ad = g_ad2[gw];

    const __half2* h2p = (const __half2*)g_h2;
    float2 acc = make_float2(0.f, 0.f);
    float dsl = 0.f;

    for (int base = 0; base < deg; base += 32) {
        int cnt = min(32, deg - base);
        if (lane < cnt) {
            int s = g_esrc[beg + base + lane];
            s_src[wb][lane] = s;
            float ev = __expf(lrelu(g_as2[s] + ad));
            s_al[wb][lane] = ev;
            dsl += ev;
        }
        __syncwarp();
        if (lane < 20) {
#pragma unroll 4
            for (int j = 0; j < cnt; j++) {
                int s = s_src[wb][j];
                float ev = s_al[wb][j];
                float2 h = __half22float2(h2p[s * 20 + lane]);
                acc.x += h.x * ev;
                acc.y += h.y * ev;
            }
        }
        __syncwarp();
    }

#pragma unroll
    for (int o = 16; o; o >>= 1) dsl += __shfl_xor_sync(0xffffffffu, dsl, o);
    float inv = __fdividef(1.f, dsl);

    if (lane < 20) {
        float2 bv = ((const float2*)b2)[lane];
        acc.x = acc.x * inv + bv.x;
        acc.y = acc.y * inv + bv.y;
        ((float2*)out)[gw * 20 + lane] = acc;
    }
}

// ---------------- launcher ----------------
extern "C" void kernel_launch(void* const* d_in, const int* in_sizes, int n_in,
                              void* d_out, int out_size)
{
    const float* x   = (const float*)d_in[0];
    const int*   ei  = (const int*)d_in[1];
    const float* W1  = (const float*)d_in[2];
    const float* as1 = (const float*)d_in[3];
    const float* ad1 = (const float*)d_in[4];
    const float* b1  = (const float*)d_in[5];
    const float* W2  = (const float*)d_in[6];
    const float* as2 = (const float*)d_in[7];
    const float* ad2 = (const float*)d_in[8];
    const float* b2  = (const float*)d_in[9];
    float* out = (float*)d_out;

    const int TB  = 256;
    const int EB  = (ET + TB - 1) / TB;
    const int NBK = (NN + TB - 1) / TB;
    const int WBK = (NN * 32 + TB - 1) / TB;

    k_zero_prep<<<NBK, TB>>>(W1, as1, ad1, W2, as2, ad2);
    k_hist<<<EB, TB>>>(ei);
    k_gemm1<<<(NN + 127) / 128, 256>>>(x);
    k_scanA<<<NB, 1024>>>();
    k_scanBC<<<NBK, TB>>>();
    k_fill<<<EB, TB>>>(ei);
    k_agg1<<<WBK, TB>>>(b1);
    k_gemm2<<<(NN + 127) / 128, 256>>>();
    k_agg2<<<WBK, TB>>>(out, b2);
}